// round 15
// baseline (speedup 1.0000x reference)
#include <cuda_runtime.h>
#include <cuda_fp16.h>
#include <math.h>
#include <stdint.h>

#define BB 2048
#define FF 64
#define DD 512
#define AA 512
#define HH 8
#define HD 64

// Prepacked weights in paired mma B-fragment order, fp16 (K32 chunks):
// [p][nt(4)][chunk(16)] blobs of 8KB;
// word idx: [ks(2)][nbp(8)][lane(32)][nbl(2)][reg(2)]  (nb = nbp*2+nbl)
__device__ uint32_t g_Wt[(size_t)3 * 4 * 16 * 2048];
// fp16 copies of query/key/value: [p][b*FF + f][k]  (402 MB)
__device__ __align__(16) __half g_Xh[(size_t)3 * BB * FF * DD];

// ---------------------------------------------------------------------------
// PTX helpers (baseline ISA only)
// ---------------------------------------------------------------------------
__device__ __forceinline__ uint32_t smem_u32(const void* p) {
    uint32_t a;
    asm("{ .reg .u64 t; cvta.to.shared.u64 t, %1; cvt.u32.u64 %0, t; }" : "=r"(a) : "l"(p));
    return a;
}
__device__ __forceinline__ void ldsm4(uint32_t* r, uint32_t addr) {
    asm volatile("ldmatrix.sync.aligned.m8n8.x4.shared.b16 {%0,%1,%2,%3}, [%4];"
                 : "=r"(r[0]), "=r"(r[1]), "=r"(r[2]), "=r"(r[3]) : "r"(addr));
}
__device__ __forceinline__ void ldsm4t(uint32_t* r, uint32_t addr) {
    asm volatile("ldmatrix.sync.aligned.m8n8.x4.trans.shared.b16 {%0,%1,%2,%3}, [%4];"
                 : "=r"(r[0]), "=r"(r[1]), "=r"(r[2]), "=r"(r[3]) : "r"(addr));
}
__device__ __forceinline__ void mma16816(float* c, const uint32_t* a, const uint32_t* b) {
    asm volatile(
        "mma.sync.aligned.m16n8k16.row.col.f32.f16.f16.f32 "
        "{%0,%1,%2,%3}, {%4,%5,%6,%7}, {%8,%9}, {%0,%1,%2,%3};"
        : "+f"(c[0]), "+f"(c[1]), "+f"(c[2]), "+f"(c[3])
        : "r"(a[0]), "r"(a[1]), "r"(a[2]), "r"(a[3]), "r"(b[0]), "r"(b[1]));
}
__device__ __forceinline__ void cpasync16(uint32_t dst, const void* src) {
    asm volatile("cp.async.cg.shared.global [%0], [%1], 16;" :: "r"(dst), "l"(src));
}
__device__ __forceinline__ uint32_t pack_h2(float a, float b) {
    return (uint32_t)__half_as_ushort(__float2half_rn(a)) |
           ((uint32_t)__half_as_ushort(__float2half_rn(b)) << 16);
}
// mbarrier primitives
#define MBAR_INIT(addr, cnt) \
    asm volatile("mbarrier.init.shared.b64 [%0], %1;" :: "r"(addr), "r"(cnt) : "memory")
#define MBAR_ARRIVE(addr) \
    asm volatile("mbarrier.arrive.shared.b64 _, [%0];" :: "r"(addr) : "memory")
#define CP_MBAR_ARRIVE(addr) \
    asm volatile("cp.async.mbarrier.arrive.noinc.shared.b64 [%0];" :: "r"(addr) : "memory")
#define MBAR_WAIT(addr, par) do { \
    uint32_t _m = (addr), _p = (par), _d; \
    asm volatile( \
        "{\n\t.reg .pred P;\n\t" \
        "mbarrier.try_wait.parity.acquire.cta.shared::cta.b64 P, [%1], %2;\n\t" \
        "selp.b32 %0, 1, 0, P;\n\t}" \
        : "=r"(_d) : "r"(_m), "r"(_p) : "memory"); \
    if (!_d) { \
        asm volatile( \
            "{\n\t.reg .pred P;\n\t" \
            "W%=:\n\t" \
            "mbarrier.try_wait.parity.acquire.cta.shared::cta.b64 P, [%0], %1, 0x989680;\n\t" \
            "@P bra.uni D%=;\n\t" \
            "bra.uni W%=;\n\t" \
            "D%=:\n\t}" \
            :: "r"(_m), "r"(_p) : "memory"); \
    } } while (0)

// ---------------------------------------------------------------------------
// Prepack: W fp32 -> fp16 in paired B-fragment order, K32. grid (16, 4, 3).
// ---------------------------------------------------------------------------
__global__ __launch_bounds__(256) void prepack_kernel(
    const float* __restrict__ Wq, const float* __restrict__ Wk, const float* __restrict__ Wv)
{
    const int c  = blockIdx.x;
    const int nt = blockIdx.y;
    const int p  = blockIdx.z;
    const float* W = (p == 0) ? Wq : (p == 1) ? Wk : Wv;
    uint32_t* dst = g_Wt + (((size_t)p * 4 + nt) * 16 + c) * 2048;

    for (int j = 0; j < 8; j++) {
        int s = threadIdx.x + j * 256;            // 0..2047
        int reg  = s & 1;
        int nbl  = (s >> 1) & 1;
        int lane = (s >> 2) & 31;
        int nbp  = (s >> 7) & 7;
        int ks   = (s >> 10) & 1;
        int nb = nbp * 2 + nbl;
        int k = c * 32 + ks * 16 + 2 * (lane & 3) + 8 * reg;
        int n = nt * 128 + nb * 8 + (lane >> 2);
        float w0 = W[(size_t)k * AA + n];
        float w1 = W[(size_t)(k + 1) * AA + n];
        dst[s] = pack_h2(w0, w1);
    }
}

// ---------------------------------------------------------------------------
// Convert X fp32 -> fp16, streaming. grid (8192, 3), 256 thr.
// ---------------------------------------------------------------------------
__global__ __launch_bounds__(256) void convx_kernel(
    const float* __restrict__ Xq, const float* __restrict__ Xk, const float* __restrict__ Xv)
{
    const int p = blockIdx.y;
    const float* X = (p == 0) ? Xq : (p == 1) ? Xk : Xv;
    __half* dst = g_Xh + (size_t)p * BB * FF * DD;
    const size_t e0 = (size_t)blockIdx.x * 8192;
    #pragma unroll
    for (int i = 0; i < 8; i++) {
        size_t idx = e0 + ((size_t)threadIdx.x + i * 256) * 4;
        float4 v = *reinterpret_cast<const float4*>(X + idx);
        uint2 h = make_uint2(pack_h2(v.x, v.y), pack_h2(v.z, v.w));
        *reinterpret_cast<uint2*>(dst + idx) = h;
    }
}

// ---------------------------------------------------------------------------
// FUSED kernel, 256 threads (8 warps). Per CTA (nt, bp): batch pair, 2 heads.
// Warp tile 32(M) x 64(N). GEMM order K, Q, V. mbarrier producer/consumer
// ring: K32 chunks, 4 buffers, 48 chunks flat across the three GEMMs —
// NO per-chunk __syncthreads, warps drift up to 3 chunks, overlapping one
// warp's smem-load phase with another's MMA phase.
// SMEM 111616 B dynamic (+64 static mbarriers):
//   XS  [0, 40960)        4 bufs x 128 rows x 80 B fp16 (VT overlays at 0)
//   BS  [40960, 73728)    4 bufs x 8 KB paired W fragment blobs
//   KT  [73728, 108544)   128 f-rows x 272 B (2 heads x 64 d fp16)
//   RED [108544, 110592)  4 x 128 fp32
//   SVS [110592, 111616)  2 x 128 fp32
//   VT  [0, 34816)        128 f-rows x 272 B
// ---------------------------------------------------------------------------
#define XS_OFF 0
#define BS_OFF 40960
#define KT_OFF 73728
#define RED_OFF 108544
#define SVS_OFF 110592
#define VT_OFF 0

__global__ __launch_bounds__(256, 2) void fused_kernel(
    const float* __restrict__ bv, const float* __restrict__ query, float* __restrict__ out)
{
    const int nt = blockIdx.x;
    const int bp = blockIdx.y;

    extern __shared__ __align__(16) unsigned char smd[];
    __shared__ __align__(8) unsigned long long s_full[4], s_empty[4];
    const uint32_t sbase = smem_u32(smd);
    const int tid   = threadIdx.x;
    const int lane  = tid & 31;
    const int wid   = tid >> 5;
    const int warpM = wid >> 1;      // 0..3
    const int warpN = wid & 1;       // 0..1 (head)

    float* red = reinterpret_cast<float*>(smd + RED_OFF);   // [4][128]
    float* svs = reinterpret_cast<float*>(smd + SVS_OFF);   // [2][128]

    uint32_t fullb[4], emptyb[4];
    #pragma unroll
    for (int i = 0; i < 4; i++) {
        fullb[i]  = smem_u32(&s_full[i]);
        emptyb[i] = smem_u32(&s_empty[i]);
    }
    if (tid == 0) {
        #pragma unroll
        for (int i = 0; i < 4; i++) {
            MBAR_INIT(fullb[i], 256u);
            MBAR_INIT(emptyb[i], 8u);
        }
    }
    __syncthreads();

    uint32_t qfr[2][4][4];           // Q as A-fragments: [mf][ks64][reg]

    // cp.async issue of one K32 chunk (X 8KB + B 8KB) into buffer `buf`,
    // then per-thread arrive-on-complete on full[buf].
    #define CPXB(Xp, Wp, c, buf) do { \
        const __half* xsrc = (Xp) + (size_t)(c) * 32; \
        _Pragma("unroll") \
        for (int i = 0; i < 2; i++) { \
            int idx = tid + i * 256;           /* 0..511 */ \
            int m  = idx >> 2; \
            int kq = idx & 3; \
            cpasync16(sbase + XS_OFF + (buf) * 10240 + m * 80 + kq * 16, \
                      xsrc + (size_t)m * DD + kq * 8); \
        } \
        const char* bsrc = reinterpret_cast<const char*>((Wp) + (size_t)(c) * 2048); \
        _Pragma("unroll") \
        for (int i = 0; i < 2; i++) { \
            int off = (tid + i * 256) * 16; \
            cpasync16(sbase + BS_OFF + (buf) * 8192 + off, bsrc + off); \
        } \
        CP_MBAR_ARRIVE(fullb[(buf)]); } while (0)

    // GEMM order K(1), Q(0), V(2); flat chunk index g = pi*16 + c, 48 total.
    // Prologue: fill all 4 buffers with chunks 0..3 of the K GEMM.
    {
        const __half* Xk = g_Xh + ((size_t)1 * BB * FF + (size_t)bp * 128) * DD;
        const uint32_t* Wk = g_Wt + (((size_t)1 * 4 + nt) * 16) * 2048;
        CPXB(Xk, Wk, 0, 0);
        CPXB(Xk, Wk, 1, 1);
        CPXB(Xk, Wk, 2, 2);
        CPXB(Xk, Wk, 3, 3);
    }

    #pragma unroll 1
    for (int pi = 0; pi < 3; ++pi) {
        const int p  = (pi == 0) ? 1 : (pi == 1) ? 0 : 2;   // K, Q, V
        const int pn = (pi == 0) ? 0 : 2;                    // next in order
        const __half* Xbh = g_Xh + ((size_t)p * BB * FF + (size_t)bp * 128) * DD;
        const uint32_t* Wg = g_Wt + (((size_t)p * 4 + nt) * 16) * 2048;
        const __half* Xn = g_Xh + ((size_t)pn * BB * FF + (size_t)bp * 128) * DD;
        const uint32_t* Wn = g_Wt + (((size_t)pn * 4 + nt) * 16) * 2048;

        float acc[2][8][4];
        #pragma unroll
        for (int mf = 0; mf < 2; mf++)
            #pragma unroll
            for (int nb = 0; nb < 8; nb++)
                #pragma unroll
                for (int r = 0; r < 4; r++) acc[mf][nb][r] = 0.f;

        #pragma unroll 1
        for (int c = 0; c < 16; ++c) {
            const int g   = pi * 16 + c;
            const int buf = g & 3;
            const uint32_t ph = (uint32_t)((g >> 2) & 1);

            MBAR_WAIT(fullb[buf], ph);

            const uint32_t abase = sbase + XS_OFF + buf * 10240;
            const uint32_t bbase = sbase + BS_OFF + buf * 8192 +
                                   (uint32_t)(warpN * 4 * 32 + lane) * 16;
            #pragma unroll
            for (int ks = 0; ks < 2; ks++) {
                uint32_t a0[4], a1[4];
                uint32_t ad = abase + (warpM * 32 + (lane & 15)) * 80 + ks * 32 + (lane >> 4) * 16;
                ldsm4(a0, ad);
                ldsm4(a1, ad + 16 * 80);
                #pragma unroll
                for (int j = 0; j < 4; j++) {
                    uint4 bb = *reinterpret_cast<const uint4*>(
                        smd + BS_OFF + buf * 8192 +
                        (uint32_t)(warpN * 4 * 32 + lane) * 16 + (uint32_t)(ks * 8 + j) * 512);
                    mma16816(acc[0][2 * j],     a0, &bb.x);
                    mma16816(acc[1][2 * j],     a1, &bb.x);
                    mma16816(acc[0][2 * j + 1], a0, &bb.z);
                    mma16816(acc[1][2 * j + 1], a1, &bb.z);
                }
            }
            (void)bbase;

            if (lane == 0) MBAR_ARRIVE(emptyb[buf]);

            if (g + 4 < 48) {
                MBAR_WAIT(emptyb[buf], ph);
                if (c < 12) CPXB(Xbh, Wg, c + 4, buf);
                else        CPXB(Xn,  Wn, c - 12, buf);
            }
        }

        // --------------------- epilogue for projection p --------------------
        // acc map: row = warpM*32 + mf*16 + (lane>>2) + 8*(r>>1),
        //          col = warpN*64 + nb*8 + 2*(lane&3) + (r&1)
        if (p < 2) {
            float cs[8][2];
            #pragma unroll
            for (int nb = 0; nb < 8; nb++) {
                cs[nb][0] = acc[0][nb][0] + acc[0][nb][2] + acc[1][nb][0] + acc[1][nb][2];
                cs[nb][1] = acc[0][nb][1] + acc[0][nb][3] + acc[1][nb][1] + acc[1][nb][3];
                #pragma unroll
                for (int d = 4; d <= 16; d <<= 1) {
                    cs[nb][0] += __shfl_xor_sync(0xFFFFFFFFu, cs[nb][0], d);
                    cs[nb][1] += __shfl_xor_sync(0xFFFFFFFFu, cs[nb][1], d);
                }
            }
            if ((lane >> 2) == 0) {
                #pragma unroll
                for (int nb = 0; nb < 8; nb++) {
                    int col = warpN * 64 + nb * 8 + 2 * (lane & 3);
                    *reinterpret_cast<float2*>(&red[warpM * 128 + col]) =
                        make_float2(cs[nb][0], cs[nb][1]);
                }
            }
            __syncthreads();
            float m0[8], m1[8];
            #pragma unroll
            for (int nb = 0; nb < 8; nb++) {
                int col = warpN * 64 + nb * 8 + 2 * (lane & 3);
                int base0 = (warpM & ~1) * 128, base1 = (warpM | 1) * 128;
                m0[nb] = (red[base0 + col]     + red[base1 + col])     * (1.f / 64.f);
                m1[nb] = (red[base0 + col + 1] + red[base1 + col + 1]) * (1.f / 64.f);
            }
            __syncthreads();
            if (p == 0) {
                // Q: keep centered fragments in registers (C-frag -> A-frag)
                #pragma unroll
                for (int mf = 0; mf < 2; mf++)
                    #pragma unroll
                    for (int ks = 0; ks < 4; ks++) {
                        qfr[mf][ks][0] = pack_h2(acc[mf][2*ks][0]   - m0[2*ks],   acc[mf][2*ks][1]   - m1[2*ks]);
                        qfr[mf][ks][1] = pack_h2(acc[mf][2*ks][2]   - m0[2*ks],   acc[mf][2*ks][3]   - m1[2*ks]);
                        qfr[mf][ks][2] = pack_h2(acc[mf][2*ks+1][0] - m0[2*ks+1], acc[mf][2*ks+1][1] - m1[2*ks+1]);
                        qfr[mf][ks][3] = pack_h2(acc[mf][2*ks+1][2] - m0[2*ks+1], acc[mf][2*ks+1][3] - m1[2*ks+1]);
                    }
            } else {
                // K: centered fp16 tile KT [f 0..127][head*64 + d]
                unsigned char* tilep = smd + KT_OFF;
                #pragma unroll
                for (int nb = 0; nb < 8; nb++) {
                    int col = warpN * 64 + nb * 8 + 2 * (lane & 3);
                    #pragma unroll
                    for (int mf = 0; mf < 2; mf++) {
                        int row0 = warpM * 32 + mf * 16 + (lane >> 2);
                        *reinterpret_cast<uint32_t*>(tilep + row0 * 272 + col * 2) =
                            pack_h2(acc[mf][nb][0] - m0[nb], acc[mf][nb][1] - m1[nb]);
                        *reinterpret_cast<uint32_t*>(tilep + (row0 + 8) * 272 + col * 2) =
                            pack_h2(acc[mf][nb][2] - m0[nb], acc[mf][nb][3] - m1[nb]);
                    }
                }
                __syncthreads();
            }
        } else {
            // V epilogue. VT overlays XS -> wait for all warps first.
            __syncthreads();

            // (a) fp16 V tile (untransposed, same layout as KT): +bv
            unsigned char* vtp = smd + VT_OFF;
            #pragma unroll
            for (int nb = 0; nb < 8; nb++) {
                int col = warpN * 64 + nb * 8 + 2 * (lane & 3);
                float2 bb = *reinterpret_cast<const float2*>(&bv[nt * 128 + col]);
                #pragma unroll
                for (int mf = 0; mf < 2; mf++) {
                    int row0 = warpM * 32 + mf * 16 + (lane >> 2);
                    *reinterpret_cast<uint32_t*>(vtp + row0 * 272 + col * 2) =
                        pack_h2(acc[mf][nb][0] + bb.x, acc[mf][nb][1] + bb.y);
                    *reinterpret_cast<uint32_t*>(vtp + (row0 + 8) * 272 + col * 2) =
                        pack_h2(acc[mf][nb][2] + bb.x, acc[mf][nb][3] + bb.y);
                }
            }

            // (b) SV = colsum(V) + 64*bv, per batch, exact in fp32
            float cs[8][2];
            #pragma unroll
            for (int nb = 0; nb < 8; nb++) {
                cs[nb][0] = acc[0][nb][0] + acc[0][nb][2] + acc[1][nb][0] + acc[1][nb][2];
                cs[nb][1] = acc[0][nb][1] + acc[0][nb][3] + acc[1][nb][1] + acc[1][nb][3];
                #pragma unroll
                for (int d = 4; d <= 16; d <<= 1) {
                    cs[nb][0] += __shfl_xor_sync(0xFFFFFFFFu, cs[nb][0], d);
                    cs[nb][1] += __shfl_xor_sync(0xFFFFFFFFu, cs[nb][1], d);
                }
            }
            if ((lane >> 2) == 0) {
                #pragma unroll
                for (int nb = 0; nb < 8; nb++) {
                    int col = warpN * 64 + nb * 8 + 2 * (lane & 3);
                    *reinterpret_cast<float2*>(&red[warpM * 128 + col]) =
                        make_float2(cs[nb][0], cs[nb][1]);
                }
            }
            __syncthreads();
            if ((lane >> 2) == 0 && (warpM & 1) == 0) {
                int batch = warpM >> 1;
                #pragma unroll
                for (int nb = 0; nb < 8; nb++) {
                    int col = warpN * 64 + nb * 8 + 2 * (lane & 3);
                    float2 bb = *reinterpret_cast<const float2*>(&bv[nt * 128 + col]);
                    float2 sv;
                    sv.x = red[warpM * 128 + col]     + red[(warpM + 1) * 128 + col]     + 64.f * bb.x;
                    sv.y = red[warpM * 128 + col + 1] + red[(warpM + 1) * 128 + col + 1] + 64.f * bb.y;
                    *reinterpret_cast<float2*>(&svs[batch * 128 + col]) = sv;
                }
            }
            __syncthreads();
        }
    }
    #undef CPXB

    // =========================== attention phase ============================
    const int batch = warpM >> 1;
    const int half  = warpM & 1;
    const int h     = warpN;
    const int b     = bp * 2 + batch;
    const int hg    = 2 * nt + h;
    const uint32_t ktb = sbase + KT_OFF;
    const uint32_t vtb = sbase + VT_OFF;

    const float* qp  = query + (size_t)b * FF * AA + hg * 64;
    float*       op  = out   + (size_t)b * FF * AA + hg * 64;

    #pragma unroll
    for (int mf = 0; mf < 2; mf++) {
        // ---- S = Qc @ Kc^T : 16(f) x 64(fk) ----
        float s[8][4];
        #pragma unroll
        for (int nb = 0; nb < 8; nb++)
            #pragma unroll
            for (int r = 0; r < 4; r++) s[nb][r] = 0.f;

        #pragma unroll
        for (int ks = 0; ks < 4; ks++) {
            uint32_t bq[4][4];
            #pragma unroll
            for (int nq = 0; nq < 4; nq++)
                ldsm4(bq[nq], ktb + (batch * 64 + nq * 16 + (lane & 15)) * 272 +
                               h * 128 + ks * 32 + (lane >> 4) * 16);
            #pragma unroll
            for (int nq = 0; nq < 4; nq++) {
                uint32_t b0[2] = {bq[nq][0], bq[nq][2]};
                uint32_t b1[2] = {bq[nq][1], bq[nq][3]};
                mma16816(s[2 * nq],     qfr[mf][ks], b0);
                mma16816(s[2 * nq + 1], qfr[mf][ks], b1);
            }
        }

        // ---- softmax on fragments ----
        #pragma unroll
        for (int hi = 0; hi < 2; hi++) {
            float mx = -INFINITY;
            #pragma unroll
            for (int nb = 0; nb < 8; nb++)
                mx = fmaxf(mx, fmaxf(s[nb][2 * hi], s[nb][2 * hi + 1]));
            mx = fmaxf(mx, __shfl_xor_sync(0xFFFFFFFFu, mx, 1));
            mx = fmaxf(mx, __shfl_xor_sync(0xFFFFFFFFu, mx, 2));
            float sum = 0.f;
            #pragma unroll
            for (int nb = 0; nb < 8; nb++) {
                float e0 = __expf(s[nb][2 * hi]     - mx);
                float e1 = __expf(s[nb][2 * hi + 1] - mx);
                s[nb][2 * hi] = e0; s[nb][2 * hi + 1] = e1;
                sum += e0 + e1;
            }
            sum += __shfl_xor_sync(0xFFFFFFFFu, sum, 1);
            sum += __shfl_xor_sync(0xFFFFFFFFu, sum, 2);
            float inv = 1.f / sum;
            #pragma unroll
            for (int nb = 0; nb < 8; nb++) {
                s[nb][2 * hi]     *= inv;
                s[nb][2 * hi + 1] *= inv;
            }
        }

        // ---- O = P @ V : P accs -> A fragments; V via ldmatrix.trans ----
        float o[8][4];
        #pragma unroll
        for (int nb = 0; nb < 8; nb++)
            #pragma unroll
            for (int r = 0; r < 4; r++) o[nb][r] = 0.f;

        #pragma unroll
        for (int kt = 0; kt < 4; kt++) {
            uint32_t pa[4];
            pa[0] = pack_h2(s[2 * kt][0],     s[2 * kt][1]);
            pa[1] = pack_h2(s[2 * kt][2],     s[2 * kt][3]);
            pa[2] = pack_h2(s[2 * kt + 1][0], s[2 * kt + 1][1]);
            pa[3] = pack_h2(s[2 * kt + 1][2], s[2 * kt + 1][3]);
            #pragma unroll
            for (int nq = 0; nq < 4; nq++) {
                uint32_t bq[4];
                ldsm4t(bq, vtb + (batch * 64 + kt * 16 + (lane & 15)) * 272 +
                            h * 128 + nq * 32 + (lane >> 4) * 16);
                mma16816(o[2 * nq],     pa, bq);
                mma16816(o[2 * nq + 1], pa, bq + 2);
            }
        }

        // ---- epilogue: out = relu(O + SV + query) ----
        #pragma unroll
        for (int nb = 0; nb < 8; nb++) {
            int d = nb * 8 + 2 * (lane & 3);
            float2 sv = *reinterpret_cast<const float2*>(&svs[batch * 128 + h * 64 + d]);
            #pragma unroll
            for (int hi = 0; hi < 2; hi++) {
                int f = half * 32 + mf * 16 + (lane >> 2) + 8 * hi;
                float2 q = *reinterpret_cast<const float2*>(qp + (size_t)f * AA + d);
                float2 r;
                r.x = fmaxf(o[nb][2 * hi]     + sv.x + q.x, 0.f);
                r.y = fmaxf(o[nb][2 * hi + 1] + sv.y + q.y, 0.f);
                *reinterpret_cast<float2*>(op + (size_t)f * AA + d) = r;
            }
        }
    }
}

// ---------------------------------------------------------------------------
extern "C" void kernel_launch(void* const* d_in, const int* in_sizes, int n_in,
                              void* d_out, int out_size)
{
    const float* query = (const float*)d_in[0];
    const float* key   = (const float*)d_in[1];
    const float* value = (const float*)d_in[2];
    const float* Wq    = (const float*)d_in[3];
    // d_in[4] (bq), d_in[6] (bk): cancel exactly under mean-centering.
    const float* Wk    = (const float*)d_in[5];
    const float* Wv    = (const float*)d_in[7];
    const float* bv    = (const float*)d_in[8];
    // d_in[9]/d_in[10] (Wk2/bk2) unused: unary softmax over size-1 axis == 1.
    float* out = (float*)d_out;

    prepack_kernel<<<dim3(16, 4, 3), 256>>>(Wq, Wk, Wv);
    convx_kernel<<<dim3(8192, 3), 256>>>(query, key, value);

    const int fused_smem = 111616;
    cudaFuncSetAttribute(fused_kernel, cudaFuncAttributeMaxDynamicSharedMemorySize, fused_smem);
    fused_kernel<<<dim3(4, BB / 2), 256, fused_smem>>>(bv, query, out);
}

// round 16
// speedup vs baseline: 1.1322x; 1.1322x over previous
#include <cuda_runtime.h>
#include <cuda_fp16.h>
#include <math.h>
#include <stdint.h>

#define BB 2048
#define FF 64
#define DD 512
#define AA 512
#define HH 8
#define HD 64

// Prepacked weights in mma B-fragment order, fp16, PAIRED for LDS.128:
// [p][nt(4)][chunk(8)] blobs of 16KB;
// blob word index: [ks(4)][nbp(8)][lane(32)][nbl(2)][reg(2)]  (nb = nbp*2+nbl)
__device__ uint32_t g_Wt[(size_t)3 * 4 * 8 * 4096];
// fp16 copies of query/key/value: [p][b*FF + f][k]  (402 MB)
__device__ __align__(16) __half g_Xh[(size_t)3 * BB * FF * DD];

// ---------------------------------------------------------------------------
// PTX helpers (baseline ISA only)
// ---------------------------------------------------------------------------
__device__ __forceinline__ uint32_t smem_u32(const void* p) {
    uint32_t a;
    asm("{ .reg .u64 t; cvta.to.shared.u64 t, %1; cvt.u32.u64 %0, t; }" : "=r"(a) : "l"(p));
    return a;
}
__device__ __forceinline__ void ldsm4(uint32_t* r, uint32_t addr) {
    asm volatile("ldmatrix.sync.aligned.m8n8.x4.shared.b16 {%0,%1,%2,%3}, [%4];"
                 : "=r"(r[0]), "=r"(r[1]), "=r"(r[2]), "=r"(r[3]) : "r"(addr));
}
__device__ __forceinline__ void ldsm4t(uint32_t* r, uint32_t addr) {
    asm volatile("ldmatrix.sync.aligned.m8n8.x4.trans.shared.b16 {%0,%1,%2,%3}, [%4];"
                 : "=r"(r[0]), "=r"(r[1]), "=r"(r[2]), "=r"(r[3]) : "r"(addr));
}
__device__ __forceinline__ void mma16816(float* c, const uint32_t* a, const uint32_t* b) {
    asm volatile(
        "mma.sync.aligned.m16n8k16.row.col.f32.f16.f16.f32 "
        "{%0,%1,%2,%3}, {%4,%5,%6,%7}, {%8,%9}, {%0,%1,%2,%3};"
        : "+f"(c[0]), "+f"(c[1]), "+f"(c[2]), "+f"(c[3])
        : "r"(a[0]), "r"(a[1]), "r"(a[2]), "r"(a[3]), "r"(b[0]), "r"(b[1]));
}
__device__ __forceinline__ void cpasync16(uint32_t dst, const void* src) {
    asm volatile("cp.async.cg.shared.global [%0], [%1], 16;" :: "r"(dst), "l"(src));
}
__device__ __forceinline__ void cp_commit() { asm volatile("cp.async.commit_group;"); }
__device__ __forceinline__ void cp_wait0()  { asm volatile("cp.async.wait_group 0;" ::: "memory"); }

__device__ __forceinline__ uint32_t pack_h2(float a, float b) {
    return (uint32_t)__half_as_ushort(__float2half_rn(a)) |
           ((uint32_t)__half_as_ushort(__float2half_rn(b)) << 16);
}

// ---------------------------------------------------------------------------
// Prepack: W fp32 -> fp16 in paired mma B-fragment order. grid (8, 4, 3).
// ---------------------------------------------------------------------------
__global__ __launch_bounds__(256) void prepack_kernel(
    const float* __restrict__ Wq, const float* __restrict__ Wk, const float* __restrict__ Wv)
{
    const int c  = blockIdx.x;
    const int nt = blockIdx.y;
    const int p  = blockIdx.z;
    const float* W = (p == 0) ? Wq : (p == 1) ? Wk : Wv;
    uint32_t* dst = g_Wt + (((size_t)p * 4 + nt) * 8 + c) * 4096;

    for (int j = 0; j < 16; j++) {
        int s = threadIdx.x + j * 256;            // 0..4095
        int reg  = s & 1;
        int nbl  = (s >> 1) & 1;
        int lane = (s >> 2) & 31;
        int nbp  = (s >> 7) & 7;
        int ks   = (s >> 10) & 3;
        int nb = nbp * 2 + nbl;
        int k = c * 64 + ks * 16 + 2 * (lane & 3) + 8 * reg;
        int n = nt * 128 + nb * 8 + (lane >> 2);
        float w0 = W[(size_t)k * AA + n];
        float w1 = W[(size_t)(k + 1) * AA + n];
        dst[s] = pack_h2(w0, w1);
    }
}

// ---------------------------------------------------------------------------
// Convert X (query/key/value) fp32 -> fp16, streaming. grid (8192, 3), 256 thr.
// ---------------------------------------------------------------------------
__global__ __launch_bounds__(256) void convx_kernel(
    const float* __restrict__ Xq, const float* __restrict__ Xk, const float* __restrict__ Xv)
{
    const int p = blockIdx.y;
    const float* X = (p == 0) ? Xq : (p == 1) ? Xk : Xv;
    __half* dst = g_Xh + (size_t)p * BB * FF * DD;
    const size_t e0 = (size_t)blockIdx.x * 8192;
    #pragma unroll
    for (int i = 0; i < 8; i++) {
        size_t idx = e0 + ((size_t)threadIdx.x + i * 256) * 4;
        float4 v = *reinterpret_cast<const float4*>(X + idx);
        uint2 h = make_uint2(pack_h2(v.x, v.y), pack_h2(v.z, v.w));
        *reinterpret_cast<uint2*>(dst + idx) = h;
    }
}

// ---------------------------------------------------------------------------
// FUSED kernel, 256 threads (8 warps). Per CTA (nt, bp): batch pair
// (2bp, 2bp+1), heads (2nt, 2nt+1). Warp tile 32(M) x 64(N):
// warpM = wid>>1 (batch = warpM>>1, half = warpM&1), warpN = wid&1 (head).
// GEMM ORDER: K, Q, V — Q's register-resident fragments (qfr) live through
// only the V mainloop. K64 chunks, double-buffered, one CTA barrier per
// chunk (R14 structure — best measured; K32 and mbarrier variants both
// regressed). Paired B fragments -> LDS.128.
// K GEMM -> centered fp16 KT. Q GEMM -> centered fragments in REGISTERS.
// V GEMM -> +bv fp16 VT (untransposed, overlays XS) + fp32 colsums -> SV.
// Attention: S = Q Kc^T, fragment softmax, O = P V (ldmatrix.trans),
// out = relu(O + SV + query_fp16)  (residual read from g_Xh, halving that
// DRAM stream; adds ~7e-5 rel_err, well within budget).
// SMEM 107520 B:
//   XS  [0, 36864)        2 bufs x 128 rows x 144 B fp16 (VT overlays at 0)
//   BS  [36864, 69632)    2 bufs x 16 KB W fragment blobs
//   KT  [69632, 104448)   128 f-rows x 272 B (2 heads x 64 d fp16)
//   RED [104448, 106496)  4 x 128 fp32 column partial sums
//   SVS [106496, 107520)  2 x 128 fp32 (per-batch SV for this head pair)
//   VT  [0, 34816)        128 f-rows x 272 B (2 heads x 64 d fp16)
// ---------------------------------------------------------------------------
#define XS_OFF 0
#define BS_OFF 36864
#define KT_OFF 69632
#define RED_OFF 104448
#define SVS_OFF 106496
#define VT_OFF 0

__global__ __launch_bounds__(256, 2) void fused_kernel(
    const float* __restrict__ bv, float* __restrict__ out)
{
    const int nt = blockIdx.x;
    const int bp = blockIdx.y;

    extern __shared__ __align__(16) unsigned char smd[];
    const uint32_t sbase = smem_u32(smd);
    const int tid   = threadIdx.x;
    const int lane  = tid & 31;
    const int wid   = tid >> 5;
    const int warpM = wid >> 1;      // 0..3
    const int warpN = wid & 1;       // 0..1 (head)

    float* red = reinterpret_cast<float*>(smd + RED_OFF);   // [4][128]
    float* svs = reinterpret_cast<float*>(smd + SVS_OFF);   // [2][128]

    uint32_t qfr[2][4][4];           // Q as A-fragments: [mf][ks][reg]

    // cp.async issue for one K64 chunk (X 16KB + B 16KB)
    #define CPXB(Xp, Wp, c, buf) do { \
        const __half* xsrc = (Xp) + (size_t)(c) * 64; \
        _Pragma("unroll") \
        for (int i = 0; i < 4; i++) { \
            int idx = tid + i * 256;           /* 0..1023 */ \
            int m  = idx >> 3; \
            int kq = idx & 7; \
            cpasync16(sbase + XS_OFF + (buf) * 18432 + m * 144 + kq * 16, \
                      xsrc + (size_t)m * DD + kq * 8); \
        } \
        const char* bsrc = reinterpret_cast<const char*>((Wp) + (size_t)(c) * 4096); \
        _Pragma("unroll") \
        for (int i = 0; i < 4; i++) { \
            int off = (tid + i * 256) * 16; \
            cpasync16(sbase + BS_OFF + (buf) * 16384 + off, bsrc + off); \
        } \
        cp_commit(); } while (0)

    // ================= three GEMMs in order K(1), Q(0), V(2) ================
    #pragma unroll 1
    for (int pi = 0; pi < 3; ++pi) {
        const int p  = (pi == 0) ? 1 : (pi == 1) ? 0 : 2;   // K, Q, V
        const int pn = (pi == 0) ? 0 : 2;                    // next in order
        const __half* Xbh = g_Xh + ((size_t)p * BB * FF + (size_t)bp * 128) * DD;
        const uint32_t* Wg = g_Wt + (((size_t)p * 4 + nt) * 8) * 4096;

        float acc[2][8][4];
        #pragma unroll
        for (int mf = 0; mf < 2; mf++)
            #pragma unroll
            for (int nb = 0; nb < 8; nb++)
                #pragma unroll
                for (int r = 0; r < 4; r++) acc[mf][nb][r] = 0.f;

        if (pi == 0) CPXB(Xbh, Wg, 0, 0);   // later GEMMs: prefetched below

        for (int c = 0; c < 8; ++c) {
            const int buf = c & 1;
            cp_wait0();
            __syncthreads();
            if (c < 7) CPXB(Xbh, Wg, c + 1, buf ^ 1);

            const uint32_t abase = sbase + XS_OFF + buf * 18432;
            #pragma unroll
            for (int ks = 0; ks < 4; ks++) {
                uint32_t a0[4], a1[4];
                uint32_t ad = abase + (warpM * 32 + (lane & 15)) * 144 + ks * 32 + (lane >> 4) * 16;
                ldsm4(a0, ad);
                ldsm4(a1, ad + 16 * 144);
                #pragma unroll
                for (int j = 0; j < 4; j++) {
                    uint4 bb = *reinterpret_cast<const uint4*>(
                        smd + BS_OFF + buf * 16384 +
                        (uint32_t)(warpN * 4 * 32 + lane) * 16 + (uint32_t)(ks * 8 + j) * 512);
                    mma16816(acc[0][2 * j],     a0, &bb.x);
                    mma16816(acc[1][2 * j],     a1, &bb.x);
                    mma16816(acc[0][2 * j + 1], a0, &bb.z);
                    mma16816(acc[1][2 * j + 1], a1, &bb.z);
                }
            }
        }

        // Prefetch chunk 0 of the next GEMM into buf 0 (safe: all warps
        // passed the c=7 barrier, so buf 0 reads of chunk 6 are done).
        if (pi < 2) {
            const __half* Xn = g_Xh + ((size_t)pn * BB * FF + (size_t)bp * 128) * DD;
            const uint32_t* Wn = g_Wt + (((size_t)pn * 4 + nt) * 8) * 4096;
            CPXB(Xn, Wn, 0, 0);
        }

        // --------------------- epilogue for projection p --------------------
        // acc map: row = warpM*32 + mf*16 + (lane>>2) + 8*(r>>1),
        //          col = warpN*64 + nb*8 + 2*(lane&3) + (r&1)
        if (p < 2) {
            float cs[8][2];
            #pragma unroll
            for (int nb = 0; nb < 8; nb++) {
                cs[nb][0] = acc[0][nb][0] + acc[0][nb][2] + acc[1][nb][0] + acc[1][nb][2];
                cs[nb][1] = acc[0][nb][1] + acc[0][nb][3] + acc[1][nb][1] + acc[1][nb][3];
                #pragma unroll
                for (int d = 4; d <= 16; d <<= 1) {
                    cs[nb][0] += __shfl_xor_sync(0xFFFFFFFFu, cs[nb][0], d);
                    cs[nb][1] += __shfl_xor_sync(0xFFFFFFFFu, cs[nb][1], d);
                }
            }
            if ((lane >> 2) == 0) {
                #pragma unroll
                for (int nb = 0; nb < 8; nb++) {
                    int col = warpN * 64 + nb * 8 + 2 * (lane & 3);
                    *reinterpret_cast<float2*>(&red[warpM * 128 + col]) =
                        make_float2(cs[nb][0], cs[nb][1]);
                }
            }
            __syncthreads();
            float m0[8], m1[8];
            #pragma unroll
            for (int nb = 0; nb < 8; nb++) {
                int col = warpN * 64 + nb * 8 + 2 * (lane & 3);
                int base0 = (warpM & ~1) * 128, base1 = (warpM | 1) * 128;
                m0[nb] = (red[base0 + col]     + red[base1 + col])     * (1.f / 64.f);
                m1[nb] = (red[base0 + col + 1] + red[base1 + col + 1]) * (1.f / 64.f);
            }
            // NOTE: no sync needed here — red is not rewritten until the next
            // GEMM's epilogue, separated by 8 chunk barriers.
            if (p == 0) {
                // Q: keep centered fragments in registers (C-frag -> A-frag)
                #pragma unroll
                for (int mf = 0; mf < 2; mf++)
                    #pragma unroll
                    for (int ks = 0; ks < 4; ks++) {
                        qfr[mf][ks][0] = pack_h2(acc[mf][2*ks][0]   - m0[2*ks],   acc[mf][2*ks][1]   - m1[2*ks]);
                        qfr[mf][ks][1] = pack_h2(acc[mf][2*ks][2]   - m0[2*ks],   acc[mf][2*ks][3]   - m1[2*ks]);
                        qfr[mf][ks][2] = pack_h2(acc[mf][2*ks+1][0] - m0[2*ks+1], acc[mf][2*ks+1][1] - m1[2*ks+1]);
                        qfr[mf][ks][3] = pack_h2(acc[mf][2*ks+1][2] - m0[2*ks+1], acc[mf][2*ks+1][3] - m1[2*ks+1]);
                    }
            } else {
                // K: centered fp16 tile KT [f 0..127][head*64 + d]
                unsigned char* tilep = smd + KT_OFF;
                #pragma unroll
                for (int nb = 0; nb < 8; nb++) {
                    int col = warpN * 64 + nb * 8 + 2 * (lane & 3);
                    #pragma unroll
                    for (int mf = 0; mf < 2; mf++) {
                        int row0 = warpM * 32 + mf * 16 + (lane >> 2);
                        *reinterpret_cast<uint32_t*>(tilep + row0 * 272 + col * 2) =
                            pack_h2(acc[mf][nb][0] - m0[nb], acc[mf][nb][1] - m1[nb]);
                        *reinterpret_cast<uint32_t*>(tilep + (row0 + 8) * 272 + col * 2) =
                            pack_h2(acc[mf][nb][2] - m0[nb], acc[mf][nb][3] - m1[nb]);
                    }
                }
                // KT reads happen in the attention phase, after many barriers.
            }
        } else {
            // V epilogue. VT overlays XS -> wait for all warps first.
            __syncthreads();

            // (a) fp16 V tile (untransposed, same layout as KT): +bv
            unsigned char* vtp = smd + VT_OFF;
            #pragma unroll
            for (int nb = 0; nb < 8; nb++) {
                int col = warpN * 64 + nb * 8 + 2 * (lane & 3);
                float2 bb = *reinterpret_cast<const float2*>(&bv[nt * 128 + col]);
                #pragma unroll
                for (int mf = 0; mf < 2; mf++) {
                    int row0 = warpM * 32 + mf * 16 + (lane >> 2);
                    *reinterpret_cast<uint32_t*>(vtp + row0 * 272 + col * 2) =
                        pack_h2(acc[mf][nb][0] + bb.x, acc[mf][nb][1] + bb.y);
                    *reinterpret_cast<uint32_t*>(vtp + (row0 + 8) * 272 + col * 2) =
                        pack_h2(acc[mf][nb][2] + bb.x, acc[mf][nb][3] + bb.y);
                }
            }

            // (b) SV = colsum(V) + 64*bv, per batch, exact in fp32
            float cs[8][2];
            #pragma unroll
            for (int nb = 0; nb < 8; nb++) {
                cs[nb][0] = acc[0][nb][0] + acc[0][nb][2] + acc[1][nb][0] + acc[1][nb][2];
                cs[nb][1] = acc[0][nb][1] + acc[0][nb][3] + acc[1][nb][1] + acc[1][nb][3];
                #pragma unroll
                for (int d = 4; d <= 16; d <<= 1) {
                    cs[nb][0] += __shfl_xor_sync(0xFFFFFFFFu, cs[nb][0], d);
                    cs[nb][1] += __shfl_xor_sync(0xFFFFFFFFu, cs[nb][1], d);
                }
            }
            if ((lane >> 2) == 0) {
                #pragma unroll
                for (int nb = 0; nb < 8; nb++) {
                    int col = warpN * 64 + nb * 8 + 2 * (lane & 3);
                    *reinterpret_cast<float2*>(&red[warpM * 128 + col]) =
                        make_float2(cs[nb][0], cs[nb][1]);
                }
            }
            __syncthreads();
            if ((lane >> 2) == 0 && (warpM & 1) == 0) {
                int batch = warpM >> 1;
                #pragma unroll
                for (int nb = 0; nb < 8; nb++) {
                    int col = warpN * 64 + nb * 8 + 2 * (lane & 3);
                    float2 bb = *reinterpret_cast<const float2*>(&bv[nt * 128 + col]);
                    float2 sv;
                    sv.x = red[warpM * 128 + col]     + red[(warpM + 1) * 128 + col]     + 64.f * bb.x;
                    sv.y = red[warpM * 128 + col + 1] + red[(warpM + 1) * 128 + col + 1] + 64.f * bb.y;
                    *reinterpret_cast<float2*>(&svs[batch * 128 + col]) = sv;
                }
            }
            __syncthreads();
        }
    }
    #undef CPXB

    // =========================== attention phase ============================
    const int batch = warpM >> 1;
    const int half  = warpM & 1;
    const int h     = warpN;
    const int b     = bp * 2 + batch;
    const int hg    = 2 * nt + h;
    const uint32_t ktb = sbase + KT_OFF;
    const uint32_t vtb = sbase + VT_OFF;

    // fp16 query residual from g_Xh (p = 0)
    const __half* qph = g_Xh + (size_t)b * FF * DD + hg * 64;
    float*        op  = out  + (size_t)b * FF * AA + hg * 64;

    #pragma unroll
    for (int mf = 0; mf < 2; mf++) {
        // ---- S = Qc @ Kc^T : 16(f) x 64(fk) ----
        float s[8][4];
        #pragma unroll
        for (int nb = 0; nb < 8; nb++)
            #pragma unroll
            for (int r = 0; r < 4; r++) s[nb][r] = 0.f;

        #pragma unroll
        for (int ks = 0; ks < 4; ks++) {
            uint32_t bq[4][4];
            #pragma unroll
            for (int nq = 0; nq < 4; nq++)
                ldsm4(bq[nq], ktb + (batch * 64 + nq * 16 + (lane & 15)) * 272 +
                               h * 128 + ks * 32 + (lane >> 4) * 16);
            #pragma unroll
            for (int nq = 0; nq < 4; nq++) {
                uint32_t b0[2] = {bq[nq][0], bq[nq][2]};
                uint32_t b1[2] = {bq[nq][1], bq[nq][3]};
                mma16816(s[2 * nq],     qfr[mf][ks], b0);
                mma16816(s[2 * nq + 1], qfr[mf][ks], b1);
            }
        }

        // ---- softmax on fragments ----
        #pragma unroll
        for (int hi = 0; hi < 2; hi++) {
            float mx = -INFINITY;
            #pragma unroll
            for (int nb = 0; nb < 8; nb++)
                mx = fmaxf(mx, fmaxf(s[nb][2 * hi], s[nb][2 * hi + 1]));
            mx = fmaxf(mx, __shfl_xor_sync(0xFFFFFFFFu, mx, 1));
            mx = fmaxf(mx, __shfl_xor_sync(0xFFFFFFFFu, mx, 2));
            float sum = 0.f;
            #pragma unroll
            for (int nb = 0; nb < 8; nb++) {
                float e0 = __expf(s[nb][2 * hi]     - mx);
                float e1 = __expf(s[nb][2 * hi + 1] - mx);
                s[nb][2 * hi] = e0; s[nb][2 * hi + 1] = e1;
                sum += e0 + e1;
            }
            sum += __shfl_xor_sync(0xFFFFFFFFu, sum, 1);
            sum += __shfl_xor_sync(0xFFFFFFFFu, sum, 2);
            float inv = 1.f / sum;
            #pragma unroll
            for (int nb = 0; nb < 8; nb++) {
                s[nb][2 * hi]     *= inv;
                s[nb][2 * hi + 1] *= inv;
            }
        }

        // ---- O = P @ V : P accs -> A fragments; V via ldmatrix.trans ----
        float o[8][4];
        #pragma unroll
        for (int nb = 0; nb < 8; nb++)
            #pragma unroll
            for (int r = 0; r < 4; r++) o[nb][r] = 0.f;

        #pragma unroll
        for (int kt = 0; kt < 4; kt++) {
            uint32_t pa[4];
            pa[0] = pack_h2(s[2 * kt][0],     s[2 * kt][1]);
            pa[1] = pack_h2(s[2 * kt][2],     s[2 * kt][3]);
            pa[2] = pack_h2(s[2 * kt + 1][0], s[2 * kt + 1][1]);
            pa[3] = pack_h2(s[2 * kt + 1][2], s[2 * kt + 1][3]);
            #pragma unroll
            for (int nq = 0; nq < 4; nq++) {
                uint32_t bq[4];
                ldsm4t(bq, vtb + (batch * 64 + kt * 16 + (lane & 15)) * 272 +
                            h * 128 + nq * 32 + (lane >> 4) * 16);
                mma16816(o[2 * nq],     pa, bq);
                mma16816(o[2 * nq + 1], pa, bq + 2);
            }
        }

        // ---- epilogue: out = relu(O + SV + query_fp16) ----
        #pragma unroll
        for (int nb = 0; nb < 8; nb++) {
            int d = nb * 8 + 2 * (lane & 3);
            float2 sv = *reinterpret_cast<const float2*>(&svs[batch * 128 + h * 64 + d]);
            #pragma unroll
            for (int hi = 0; hi < 2; hi++) {
                int f = half * 32 + mf * 16 + (lane >> 2) + 8 * hi;
                __half2 qh = *reinterpret_cast<const __half2*>(qph + (size_t)f * DD + d);
                float2 q = __half22float2(qh);
                float2 r;
                r.x = fmaxf(o[nb][2 * hi]     + sv.x + q.x, 0.f);
                r.y = fmaxf(o[nb][2 * hi + 1] + sv.y + q.y, 0.f);
                *reinterpret_cast<float2*>(op + (size_t)f * AA + d) = r;
            }
        }
    }
}

// ---------------------------------------------------------------------------
extern "C" void kernel_launch(void* const* d_in, const int* in_sizes, int n_in,
                              void* d_out, int out_size)
{
    const float* query = (const float*)d_in[0];
    const float* key   = (const float*)d_in[1];
    const float* value = (const float*)d_in[2];
    const float* Wq    = (const float*)d_in[3];
    // d_in[4] (bq), d_in[6] (bk): cancel exactly under mean-centering.
    const float* Wk    = (const float*)d_in[5];
    const float* Wv    = (const float*)d_in[7];
    const float* bv    = (const float*)d_in[8];
    // d_in[9]/d_in[10] (Wk2/bk2) unused: unary softmax over size-1 axis == 1.
    float* out = (float*)d_out;

    prepack_kernel<<<dim3(8, 4, 3), 256>>>(Wq, Wk, Wv);
    convx_kernel<<<dim3(8192, 3), 256>>>(query, key, value);

    const int fused_smem = 107520;
    cudaFuncSetAttribute(fused_kernel, cudaFuncAttributeMaxDynamicSharedMemorySize, fused_smem);
    fused_kernel<<<dim3(4, BB / 2), 256, fused_smem>>>(bv, out);
}

// round 17
// speedup vs baseline: 1.1405x; 1.0073x over previous
#include <cuda_runtime.h>
#include <cuda_fp16.h>
#include <math.h>
#include <stdint.h>

#define BB 2048
#define FF 64
#define DD 512
#define AA 512
#define HH 8
#define HD 64

// Prepacked weights in mma B-fragment order, fp16, PAIRED for LDS.128:
// [p][nt(4)][chunk(8)] blobs of 16KB;
// blob word index: [ks(4)][nbp(8)][lane(32)][nbl(2)][reg(2)]  (nb = nbp*2+nbl)
__device__ uint32_t g_Wt[(size_t)3 * 4 * 8 * 4096];
// fp16 copies of query/key/value: [p][b*FF + f][k]  (402 MB)
__device__ __align__(16) __half g_Xh[(size_t)3 * BB * FF * DD];

// ---------------------------------------------------------------------------
// PTX helpers (baseline ISA only)
// ---------------------------------------------------------------------------
__device__ __forceinline__ uint32_t smem_u32(const void* p) {
    uint32_t a;
    asm("{ .reg .u64 t; cvta.to.shared.u64 t, %1; cvt.u32.u64 %0, t; }" : "=r"(a) : "l"(p));
    return a;
}
__device__ __forceinline__ void ldsm4(uint32_t* r, uint32_t addr) {
    asm volatile("ldmatrix.sync.aligned.m8n8.x4.shared.b16 {%0,%1,%2,%3}, [%4];"
                 : "=r"(r[0]), "=r"(r[1]), "=r"(r[2]), "=r"(r[3]) : "r"(addr));
}
__device__ __forceinline__ void ldsm4t(uint32_t* r, uint32_t addr) {
    asm volatile("ldmatrix.sync.aligned.m8n8.x4.trans.shared.b16 {%0,%1,%2,%3}, [%4];"
                 : "=r"(r[0]), "=r"(r[1]), "=r"(r[2]), "=r"(r[3]) : "r"(addr));
}
__device__ __forceinline__ void mma16816(float* c, const uint32_t* a, const uint32_t* b) {
    asm volatile(
        "mma.sync.aligned.m16n8k16.row.col.f32.f16.f16.f32 "
        "{%0,%1,%2,%3}, {%4,%5,%6,%7}, {%8,%9}, {%0,%1,%2,%3};"
        : "+f"(c[0]), "+f"(c[1]), "+f"(c[2]), "+f"(c[3])
        : "r"(a[0]), "r"(a[1]), "r"(a[2]), "r"(a[3]), "r"(b[0]), "r"(b[1]));
}
__device__ __forceinline__ void cpasync16(uint32_t dst, const void* src) {
    asm volatile("cp.async.cg.shared.global [%0], [%1], 16;" :: "r"(dst), "l"(src));
}
__device__ __forceinline__ void cp_commit() { asm volatile("cp.async.commit_group;"); }
__device__ __forceinline__ void cp_wait0()  { asm volatile("cp.async.wait_group 0;" ::: "memory"); }

__device__ __forceinline__ uint32_t pack_h2(float a, float b) {
    return (uint32_t)__half_as_ushort(__float2half_rn(a)) |
           ((uint32_t)__half_as_ushort(__float2half_rn(b)) << 16);
}

// ---------------------------------------------------------------------------
// Prepack: W fp32 -> fp16 in paired mma B-fragment order. grid (8, 4, 3).
// ---------------------------------------------------------------------------
__global__ __launch_bounds__(256) void prepack_kernel(
    const float* __restrict__ Wq, const float* __restrict__ Wk, const float* __restrict__ Wv)
{
    const int c  = blockIdx.x;
    const int nt = blockIdx.y;
    const int p  = blockIdx.z;
    const float* W = (p == 0) ? Wq : (p == 1) ? Wk : Wv;
    uint32_t* dst = g_Wt + (((size_t)p * 4 + nt) * 8 + c) * 4096;

    for (int j = 0; j < 16; j++) {
        int s = threadIdx.x + j * 256;            // 0..4095
        int reg  = s & 1;
        int nbl  = (s >> 1) & 1;
        int lane = (s >> 2) & 31;
        int nbp  = (s >> 7) & 7;
        int ks   = (s >> 10) & 3;
        int nb = nbp * 2 + nbl;
        int k = c * 64 + ks * 16 + 2 * (lane & 3) + 8 * reg;
        int n = nt * 128 + nb * 8 + (lane >> 2);
        float w0 = W[(size_t)k * AA + n];
        float w1 = W[(size_t)(k + 1) * AA + n];
        dst[s] = pack_h2(w0, w1);
    }
}

// ---------------------------------------------------------------------------
// Convert X (query/key/value) fp32 -> fp16, streaming. grid (8192, 3), 256 thr.
// ---------------------------------------------------------------------------
__global__ __launch_bounds__(256) void convx_kernel(
    const float* __restrict__ Xq, const float* __restrict__ Xk, const float* __restrict__ Xv)
{
    const int p = blockIdx.y;
    const float* X = (p == 0) ? Xq : (p == 1) ? Xk : Xv;
    __half* dst = g_Xh + (size_t)p * BB * FF * DD;
    const size_t e0 = (size_t)blockIdx.x * 8192;
    #pragma unroll
    for (int i = 0; i < 8; i++) {
        size_t idx = e0 + ((size_t)threadIdx.x + i * 256) * 4;
        float4 v = *reinterpret_cast<const float4*>(X + idx);
        uint2 h = make_uint2(pack_h2(v.x, v.y), pack_h2(v.z, v.w));
        *reinterpret_cast<uint2*>(dst + idx) = h;
    }
}

// ---------------------------------------------------------------------------
// FUSED kernel, 256 threads (8 warps). Per CTA (nt, bp): batch pair
// (2bp, 2bp+1), heads (2nt, 2nt+1). Warp tile 32(M) x 64(N):
// warpM = wid>>1 (batch = warpM>>1, half = warpM&1), warpN = wid&1 (head).
// GEMM ORDER: K, Q, V. K64 chunks, double-buffered, one CTA barrier per
// chunk (best measured). Paired B fragments -> LDS.128.
// K GEMM -> centered fp16 KT. Q GEMM -> centered fragments; S = Q Kc^T +
// softmax + fp16 P-pack run IMMEDIATELY (hidden under the V chunk-0
// prefetch). V GEMM -> +bv fp16 VT + fp32 colsums -> SV. Tail: O = P V,
// out = relu(O + SV + query_fp16).
// SMEM 107520 B:
//   XS  [0, 36864)        2 bufs x 128 rows x 144 B fp16 (VT overlays at 0)
//   BS  [36864, 69632)    2 bufs x 16 KB W fragment blobs
//   KT  [69632, 104448)   128 f-rows x 272 B (2 heads x 64 d fp16)
//   RED [104448, 106496)  4 x 128 fp32 column partial sums
//   SVS [106496, 107520)  2 x 128 fp32 (per-batch SV for this head pair)
//   VT  [0, 34816)        128 f-rows x 272 B (2 heads x 64 d fp16)
// ---------------------------------------------------------------------------
#define XS_OFF 0
#define BS_OFF 36864
#define KT_OFF 69632
#define RED_OFF 104448
#define SVS_OFF 106496
#define VT_OFF 0

__global__ __launch_bounds__(256, 2) void fused_kernel(
    const float* __restrict__ bv, float* __restrict__ out)
{
    const int nt = blockIdx.x;
    const int bp = blockIdx.y;

    extern __shared__ __align__(16) unsigned char smd[];
    const uint32_t sbase = smem_u32(smd);
    const int tid   = threadIdx.x;
    const int lane  = tid & 31;
    const int wid   = tid >> 5;
    const int warpM = wid >> 1;      // 0..3
    const int warpN = wid & 1;       // 0..1 (head)
    const int batch = warpM >> 1;
    const int half  = warpM & 1;
    const int h     = warpN;

    float* red = reinterpret_cast<float*>(smd + RED_OFF);   // [4][128]
    float* svs = reinterpret_cast<float*>(smd + SVS_OFF);   // [2][128]
    const uint32_t ktb = sbase + KT_OFF;
    const uint32_t vtb = sbase + VT_OFF;

    uint32_t pa[2][4][4];            // softmaxed P as fp16 A-fragments

    // cp.async issue for one K64 chunk (X 16KB + B 16KB)
    #define CPXB(Xp, Wp, c, buf) do { \
        const __half* xsrc = (Xp) + (size_t)(c) * 64; \
        _Pragma("unroll") \
        for (int i = 0; i < 4; i++) { \
            int idx = tid + i * 256;           /* 0..1023 */ \
            int m  = idx >> 3; \
            int kq = idx & 7; \
            cpasync16(sbase + XS_OFF + (buf) * 18432 + m * 144 + kq * 16, \
                      xsrc + (size_t)m * DD + kq * 8); \
        } \
        const char* bsrc = reinterpret_cast<const char*>((Wp) + (size_t)(c) * 4096); \
        _Pragma("unroll") \
        for (int i = 0; i < 4; i++) { \
            int off = (tid + i * 256) * 16; \
            cpasync16(sbase + BS_OFF + (buf) * 16384 + off, bsrc + off); \
        } \
        cp_commit(); } while (0)

    // ================= three GEMMs in order K(1), Q(0), V(2) ================
    #pragma unroll 1
    for (int pi = 0; pi < 3; ++pi) {
        const int p  = (pi == 0) ? 1 : (pi == 1) ? 0 : 2;   // K, Q, V
        const int pn = (pi == 0) ? 0 : 2;                    // next in order
        const __half* Xbh = g_Xh + ((size_t)p * BB * FF + (size_t)bp * 128) * DD;
        const uint32_t* Wg = g_Wt + (((size_t)p * 4 + nt) * 8) * 4096;

        float acc[2][8][4];
        #pragma unroll
        for (int mf = 0; mf < 2; mf++)
            #pragma unroll
            for (int nb = 0; nb < 8; nb++)
                #pragma unroll
                for (int r = 0; r < 4; r++) acc[mf][nb][r] = 0.f;

        if (pi == 0) CPXB(Xbh, Wg, 0, 0);   // later GEMMs: prefetched below

        #pragma unroll
        for (int c = 0; c < 8; ++c) {
            const int buf = c & 1;
            cp_wait0();
            __syncthreads();
            if (c < 7) CPXB(Xbh, Wg, c + 1, buf ^ 1);

            const uint32_t abase = sbase + XS_OFF + buf * 18432;
            #pragma unroll
            for (int ks = 0; ks < 4; ks++) {
                uint32_t a0[4], a1[4];
                uint32_t ad = abase + (warpM * 32 + (lane & 15)) * 144 + ks * 32 + (lane >> 4) * 16;
                ldsm4(a0, ad);
                ldsm4(a1, ad + 16 * 144);
                #pragma unroll
                for (int j = 0; j < 4; j++) {
                    uint4 bb = *reinterpret_cast<const uint4*>(
                        smd + BS_OFF + buf * 16384 +
                        (uint32_t)(warpN * 4 * 32 + lane) * 16 + (uint32_t)(ks * 8 + j) * 512);
                    mma16816(acc[0][2 * j],     a0, &bb.x);
                    mma16816(acc[1][2 * j],     a1, &bb.x);
                    mma16816(acc[0][2 * j + 1], a0, &bb.z);
                    mma16816(acc[1][2 * j + 1], a1, &bb.z);
                }
            }
        }

        // Prefetch chunk 0 of the next GEMM into buf 0 (safe: all warps
        // passed the c=7 barrier, so buf 0 reads of chunk 6 are done).
        // The Q epilogue + S/softmax below run in this prefetch's shadow.
        if (pi < 2) {
            const __half* Xn = g_Xh + ((size_t)pn * BB * FF + (size_t)bp * 128) * DD;
            const uint32_t* Wn = g_Wt + (((size_t)pn * 4 + nt) * 8) * 4096;
            CPXB(Xn, Wn, 0, 0);
        }

        // --------------------- epilogue for projection p --------------------
        // acc map: row = warpM*32 + mf*16 + (lane>>2) + 8*(r>>1),
        //          col = warpN*64 + nb*8 + 2*(lane&3) + (r&1)
        if (p < 2) {
            float cs[8][2];
            #pragma unroll
            for (int nb = 0; nb < 8; nb++) {
                cs[nb][0] = acc[0][nb][0] + acc[0][nb][2] + acc[1][nb][0] + acc[1][nb][2];
                cs[nb][1] = acc[0][nb][1] + acc[0][nb][3] + acc[1][nb][1] + acc[1][nb][3];
                #pragma unroll
                for (int d = 4; d <= 16; d <<= 1) {
                    cs[nb][0] += __shfl_xor_sync(0xFFFFFFFFu, cs[nb][0], d);
                    cs[nb][1] += __shfl_xor_sync(0xFFFFFFFFu, cs[nb][1], d);
                }
            }
            if ((lane >> 2) == 0) {
                #pragma unroll
                for (int nb = 0; nb < 8; nb++) {
                    int col = warpN * 64 + nb * 8 + 2 * (lane & 3);
                    *reinterpret_cast<float2*>(&red[warpM * 128 + col]) =
                        make_float2(cs[nb][0], cs[nb][1]);
                }
            }
            __syncthreads();
            float m0[8], m1[8];
            #pragma unroll
            for (int nb = 0; nb < 8; nb++) {
                int col = warpN * 64 + nb * 8 + 2 * (lane & 3);
                int base0 = (warpM & ~1) * 128, base1 = (warpM | 1) * 128;
                m0[nb] = (red[base0 + col]     + red[base1 + col])     * (1.f / 64.f);
                m1[nb] = (red[base0 + col + 1] + red[base1 + col + 1]) * (1.f / 64.f);
            }
            // no sync needed: red is next rewritten only after 8 chunk barriers
            if (p == 0) {
                // Q: centered C-frags -> A-frags (short-lived), then
                // S = Q Kc^T + softmax + P-pack, hidden under V chunk-0 load.
                uint32_t qfr[2][4][4];
                #pragma unroll
                for (int mf = 0; mf < 2; mf++)
                    #pragma unroll
                    for (int ks = 0; ks < 4; ks++) {
                        qfr[mf][ks][0] = pack_h2(acc[mf][2*ks][0]   - m0[2*ks],   acc[mf][2*ks][1]   - m1[2*ks]);
                        qfr[mf][ks][1] = pack_h2(acc[mf][2*ks][2]   - m0[2*ks],   acc[mf][2*ks][3]   - m1[2*ks]);
                        qfr[mf][ks][2] = pack_h2(acc[mf][2*ks+1][0] - m0[2*ks+1], acc[mf][2*ks+1][1] - m1[2*ks+1]);
                        qfr[mf][ks][3] = pack_h2(acc[mf][2*ks+1][2] - m0[2*ks+1], acc[mf][2*ks+1][3] - m1[2*ks+1]);
                    }

                #pragma unroll
                for (int mf = 0; mf < 2; mf++) {
                    // ---- S = Qc @ Kc^T : 16(f) x 64(fk), KT from K GEMM ----
                    float s[8][4];
                    #pragma unroll
                    for (int nb = 0; nb < 8; nb++)
                        #pragma unroll
                        for (int r = 0; r < 4; r++) s[nb][r] = 0.f;

                    #pragma unroll
                    for (int ks = 0; ks < 4; ks++) {
                        uint32_t bq[4][4];
                        #pragma unroll
                        for (int nq = 0; nq < 4; nq++)
                            ldsm4(bq[nq], ktb + (batch * 64 + nq * 16 + (lane & 15)) * 272 +
                                           h * 128 + ks * 32 + (lane >> 4) * 16);
                        #pragma unroll
                        for (int nq = 0; nq < 4; nq++) {
                            uint32_t b0[2] = {bq[nq][0], bq[nq][2]};
                            uint32_t b1[2] = {bq[nq][1], bq[nq][3]};
                            mma16816(s[2 * nq],     qfr[mf][ks], b0);
                            mma16816(s[2 * nq + 1], qfr[mf][ks], b1);
                        }
                    }

                    // ---- softmax on fragments ----
                    #pragma unroll
                    for (int hi = 0; hi < 2; hi++) {
                        float mx = -INFINITY;
                        #pragma unroll
                        for (int nb = 0; nb < 8; nb++)
                            mx = fmaxf(mx, fmaxf(s[nb][2 * hi], s[nb][2 * hi + 1]));
                        mx = fmaxf(mx, __shfl_xor_sync(0xFFFFFFFFu, mx, 1));
                        mx = fmaxf(mx, __shfl_xor_sync(0xFFFFFFFFu, mx, 2));
                        float sum = 0.f;
                        #pragma unroll
                        for (int nb = 0; nb < 8; nb++) {
                            float e0 = __expf(s[nb][2 * hi]     - mx);
                            float e1 = __expf(s[nb][2 * hi + 1] - mx);
                            s[nb][2 * hi] = e0; s[nb][2 * hi + 1] = e1;
                            sum += e0 + e1;
                        }
                        sum += __shfl_xor_sync(0xFFFFFFFFu, sum, 1);
                        sum += __shfl_xor_sync(0xFFFFFFFFu, sum, 2);
                        float inv = 1.f / sum;
                        #pragma unroll
                        for (int nb = 0; nb < 8; nb++) {
                            s[nb][2 * hi]     *= inv;
                            s[nb][2 * hi + 1] *= inv;
                        }
                    }

                    // ---- pack P into fp16 A-fragments ----
                    #pragma unroll
                    for (int kt = 0; kt < 4; kt++) {
                        pa[mf][kt][0] = pack_h2(s[2 * kt][0],     s[2 * kt][1]);
                        pa[mf][kt][1] = pack_h2(s[2 * kt][2],     s[2 * kt][3]);
                        pa[mf][kt][2] = pack_h2(s[2 * kt + 1][0], s[2 * kt + 1][1]);
                        pa[mf][kt][3] = pack_h2(s[2 * kt + 1][2], s[2 * kt + 1][3]);
                    }
                }
            } else {
                // K: centered fp16 tile KT [f 0..127][head*64 + d]
                unsigned char* tilep = smd + KT_OFF;
                #pragma unroll
                for (int nb = 0; nb < 8; nb++) {
                    int col = warpN * 64 + nb * 8 + 2 * (lane & 3);
                    #pragma unroll
                    for (int mf = 0; mf < 2; mf++) {
                        int row0 = warpM * 32 + mf * 16 + (lane >> 2);
                        *reinterpret_cast<uint32_t*>(tilep + row0 * 272 + col * 2) =
                            pack_h2(acc[mf][nb][0] - m0[nb], acc[mf][nb][1] - m1[nb]);
                        *reinterpret_cast<uint32_t*>(tilep + (row0 + 8) * 272 + col * 2) =
                            pack_h2(acc[mf][nb][2] - m0[nb], acc[mf][nb][3] - m1[nb]);
                    }
                }
                // KT reads happen after the Q GEMM's 8 chunk barriers.
            }
        } else {
            // V epilogue. VT overlays XS -> wait for all warps first.
            __syncthreads();

            // (a) fp16 V tile (untransposed, same layout as KT): +bv
            unsigned char* vtp = smd + VT_OFF;
            #pragma unroll
            for (int nb = 0; nb < 8; nb++) {
                int col = warpN * 64 + nb * 8 + 2 * (lane & 3);
                float2 bb = *reinterpret_cast<const float2*>(&bv[nt * 128 + col]);
                #pragma unroll
                for (int mf = 0; mf < 2; mf++) {
                    int row0 = warpM * 32 + mf * 16 + (lane >> 2);
                    *reinterpret_cast<uint32_t*>(vtp + row0 * 272 + col * 2) =
                        pack_h2(acc[mf][nb][0] + bb.x, acc[mf][nb][1] + bb.y);
                    *reinterpret_cast<uint32_t*>(vtp + (row0 + 8) * 272 + col * 2) =
                        pack_h2(acc[mf][nb][2] + bb.x, acc[mf][nb][3] + bb.y);
                }
            }

            // (b) SV = colsum(V) + 64*bv, per batch, exact in fp32
            float cs[8][2];
            #pragma unroll
            for (int nb = 0; nb < 8; nb++) {
                cs[nb][0] = acc[0][nb][0] + acc[0][nb][2] + acc[1][nb][0] + acc[1][nb][2];
                cs[nb][1] = acc[0][nb][1] + acc[0][nb][3] + acc[1][nb][1] + acc[1][nb][3];
                #pragma unroll
                for (int d = 4; d <= 16; d <<= 1) {
                    cs[nb][0] += __shfl_xor_sync(0xFFFFFFFFu, cs[nb][0], d);
                    cs[nb][1] += __shfl_xor_sync(0xFFFFFFFFu, cs[nb][1], d);
                }
            }
            if ((lane >> 2) == 0) {
                #pragma unroll
                for (int nb = 0; nb < 8; nb++) {
                    int col = warpN * 64 + nb * 8 + 2 * (lane & 3);
                    *reinterpret_cast<float2*>(&red[warpM * 128 + col]) =
                        make_float2(cs[nb][0], cs[nb][1]);
                }
            }
            __syncthreads();
            if ((lane >> 2) == 0 && (warpM & 1) == 0) {
                int bt = warpM >> 1;
                #pragma unroll
                for (int nb = 0; nb < 8; nb++) {
                    int col = warpN * 64 + nb * 8 + 2 * (lane & 3);
                    float2 bb = *reinterpret_cast<const float2*>(&bv[nt * 128 + col]);
                    float2 sv;
                    sv.x = red[warpM * 128 + col]     + red[(warpM + 1) * 128 + col]     + 64.f * bb.x;
                    sv.y = red[warpM * 128 + col + 1] + red[(warpM + 1) * 128 + col + 1] + 64.f * bb.y;
                    *reinterpret_cast<float2*>(&svs[bt * 128 + col]) = sv;
                }
            }
            __syncthreads();
        }
    }
    #undef CPXB

    // =================== attention tail: O = P V + epilogue ==================
    const int b  = bp * 2 + batch;
    const int hg = 2 * nt + h;

    // fp16 query residual from g_Xh (p = 0)
    const __half* qph = g_Xh + (size_t)b * FF * DD + hg * 64;
    float*        op  = out  + (size_t)b * FF * AA + hg * 64;

    #pragma unroll
    for (int mf = 0; mf < 2; mf++) {
        float o[8][4];
        #pragma unroll
        for (int nb = 0; nb < 8; nb++)
            #pragma unroll
            for (int r = 0; r < 4; r++) o[nb][r] = 0.f;

        #pragma unroll
        for (int kt = 0; kt < 4; kt++) {
            #pragma unroll
            for (int nq = 0; nq < 4; nq++) {
                uint32_t bq[4];
                ldsm4t(bq, vtb + (batch * 64 + kt * 16 + (lane & 15)) * 272 +
                            h * 128 + nq * 32 + (lane >> 4) * 16);
                mma16816(o[2 * nq],     pa[mf][kt], bq);
                mma16816(o[2 * nq + 1], pa[mf][kt], bq + 2);
            }
        }

        // ---- epilogue: out = relu(O + SV + query_fp16) ----
        #pragma unroll
        for (int nb = 0; nb < 8; nb++) {
            int d = nb * 8 + 2 * (lane & 3);
            float2 sv = *reinterpret_cast<const float2*>(&svs[batch * 128 + h * 64 + d]);
            #pragma unroll
            for (int hi = 0; hi < 2; hi++) {
                int f = half * 32 + mf * 16 + (lane >> 2) + 8 * hi;
                __half2 qh = *reinterpret_cast<const __half2*>(qph + (size_t)f * DD + d);
                float2 q = __half22float2(qh);
                float2 r;
                r.x = fmaxf(o[nb][2 * hi]     + sv.x + q.x, 0.f);
                r.y = fmaxf(o[nb][2 * hi + 1] + sv.y + q.y, 0.f);
                *reinterpret_cast<float2*>(op + (size_t)f * AA + d) = r;
            }
        }
    }
}

// ---------------------------------------------------------------------------
extern "C" void kernel_launch(void* const* d_in, const int* in_sizes, int n_in,
                              void* d_out, int out_size)
{
    const float* query = (const float*)d_in[0];
    const float* key   = (const float*)d_in[1];
    const float* value = (const float*)d_in[2];
    const float* Wq    = (const float*)d_in[3];
    // d_in[4] (bq), d_in[6] (bk): cancel exactly under mean-centering.
    const float* Wk    = (const float*)d_in[5];
    const float* Wv    = (const float*)d_in[7];
    const float* bv    = (const float*)d_in[8];
    // d_in[9]/d_in[10] (Wk2/bk2) unused: unary softmax over size-1 axis == 1.
    float* out = (float*)d_out;

    prepack_kernel<<<dim3(8, 4, 3), 256>>>(Wq, Wk, Wv);
    convx_kernel<<<dim3(8192, 3), 256>>>(query, key, value);

    const int fused_smem = 107520;
    cudaFuncSetAttribute(fused_kernel, cudaFuncAttributeMaxDynamicSharedMemorySize, fused_smem);
    fused_kernel<<<dim3(4, BB / 2), 256, fused_smem>>>(bv, out);
}